// round 1
// baseline (speedup 1.0000x reference)
#include <cuda_runtime.h>

#define B_    8
#define V_    4096
#define P_    32
#define CIN   64
#define R_    2
#define NSH   16
#define COUT  128
#define BV    (B_ * V_)      // 32768
#define K2    (CIN * R_ * 4) // 512

// 64 MB scratch for ypow [BV][K2], k = c*8 + r*4 + l  (matches W flattening)
__device__ float g_ypow[(size_t)BV * K2];

__device__ __forceinline__ float sqclip(float x) {
    return sqrtf(fmaxf(x, 1e-4f));
}

// ---------------------------------------------------------------------------
// Kernel 1: per-(b,v) gather + 32x64x32 GEMM + SH power spectrum + sqrt
// One warp per (b,v); 4 warps (4 bv) per CTA. 48 KB smem.
// ---------------------------------------------------------------------------
__global__ __launch_bounds__(128, 4)
void ypow_kernel(const float* __restrict__ signal,
                 const int*   __restrict__ pidx,
                 const float* __restrict__ convk)
{
    __shared__ float sA[4][P_ * 32];   // [warp][p][rn]  4 KB each
    __shared__ float sS[4][P_ * CIN];  // [warp][p][c]   8 KB each

    const int g    = threadIdx.x >> 5;
    const int lane = threadIdx.x & 31;
    const int bv   = blockIdx.x * 4 + g;

    // Load conv_kernel[bv]: 1024 floats, coalesced float4
    {
        const float4* src = (const float4*)(convk + (size_t)bv * (P_ * 32));
        float4* dst = (float4*)sA[g];
        #pragma unroll
        for (int j = 0; j < 8; ++j)
            dst[j * 32 + lane] = src[j * 32 + lane];
    }
    // Gather signal rows: lane p loads its 256 B row (L2-resident)
    {
        const int2 ip = ((const int2*)pidx)[bv * P_ + lane];
        const float4* srow = (const float4*)(signal + ((size_t)ip.x * V_ + (size_t)ip.y) * CIN);
        float4* dst = (float4*)(sS[g] + lane * CIN);
        #pragma unroll
        for (int j = 0; j < 16; ++j)
            dst[j] = srow[j];
    }
    __syncthreads();

    // Thread tile: 8 c's x 8 rn's.  cb in [0,8), nb in [0,4)
    const int cb = lane & 7;
    const int nb = lane >> 3;

    float acc[8][8];
    #pragma unroll
    for (int i = 0; i < 8; ++i)
        #pragma unroll
        for (int j = 0; j < 8; ++j)
            acc[i][j] = 0.0f;

    const float4* A4 = (const float4*)sA[g];
    const float4* S4 = (const float4*)sS[g];

    #pragma unroll 4
    for (int k = 0; k < P_; ++k) {
        float4 a0 = A4[k * 8  + nb * 2];
        float4 a1 = A4[k * 8  + nb * 2 + 1];
        float4 s0 = S4[k * 16 + cb * 2];
        float4 s1 = S4[k * 16 + cb * 2 + 1];
        float a[8] = {a0.x, a0.y, a0.z, a0.w, a1.x, a1.y, a1.z, a1.w};
        float s[8] = {s0.x, s0.y, s0.z, s0.w, s1.x, s1.y, s1.z, s1.w};
        #pragma unroll
        for (int ci = 0; ci < 8; ++ci)
            #pragma unroll
            for (int ni = 0; ni < 8; ++ni)
                acc[ci][ni] += s[ci] * a[ni];
    }

    // Epilogue: square + per-l sums.
    // rn = nb*8 + ni  ->  r = nb>>1,  n = (nb&1)*8 + ni
    // l-blocks over n: l0={0}, l1={1..3}, l2={4..8}, l3={9..15}
    // even half (n 0..7): full l0, l1 and l2-part {4..7}
    // odd  half (n 8..15): l2-part {8} and full l3
    const int r   = nb >> 1;
    const int odd = nb & 1;
    float* outp = g_ypow + (size_t)bv * K2;

    float t0[8], t1[8], l2p[8];
    #pragma unroll
    for (int ci = 0; ci < 8; ++ci) {
        float q[8];
        #pragma unroll
        for (int ni = 0; ni < 8; ++ni) q[ni] = acc[ci][ni] * acc[ci][ni];
        if (!odd) {
            t0[ci]  = q[0];
            t1[ci]  = q[1] + q[2] + q[3];
            l2p[ci] = q[4] + q[5] + q[6] + q[7];
        } else {
            l2p[ci] = q[0];
            t1[ci]  = q[1] + q[2] + q[3] + q[4] + q[5] + q[6] + q[7];
        }
    }
    #pragma unroll
    for (int ci = 0; ci < 8; ++ci) {
        float other = __shfl_down_sync(0xffffffffu, l2p[ci], 8);
        const int c = cb * 8 + ci;
        float* o = outp + c * 8 + r * 4;
        if (!odd) {
            o[0] = sqclip(t0[ci]);
            o[1] = sqclip(t1[ci]);
            o[2] = sqclip(l2p[ci] + other);
        } else {
            o[3] = sqclip(t1[ci]);
        }
    }
}

// ---------------------------------------------------------------------------
// Kernel 2: out[32768,128] = ypow[32768,512] * W[128,512]^T + bias, relu
// CTA: 128(M) x 128(N) tile, kT=32, 256 threads, 8x8 micro-tiles.
// ---------------------------------------------------------------------------
__global__ __launch_bounds__(256, 2)
void out_gemm_kernel(const float* __restrict__ W,
                     const float* __restrict__ bias,
                     float* __restrict__ out)
{
    __shared__ float sA[32][128];
    __shared__ float sB[32][128];
    __shared__ float sbias[COUT];

    const int tid = threadIdx.x;
    const int m0  = blockIdx.x * 128;

    if (tid < COUT) sbias[tid] = bias[tid];

    const int rowq = tid >> 3;          // 0..31
    const int kq   = tid & 7;           // 0..7 (float4 within 32-k tile)
    const int tm   = (tid >> 4) * 8;    // 0..120
    const int tn   = (tid & 15) * 8;    // 0..120

    float acc[8][8];
    #pragma unroll
    for (int i = 0; i < 8; ++i)
        #pragma unroll
        for (int j = 0; j < 8; ++j)
            acc[i][j] = 0.0f;

    for (int kt = 0; kt < K2 / 32; ++kt) {
        __syncthreads();
        // A tile: ypow rows, transposed into sA[k][m]
        #pragma unroll
        for (int rr = 0; rr < 4; ++rr) {
            int row = rowq + rr * 32;
            float4 v = *(const float4*)(g_ypow + (size_t)(m0 + row) * K2 + kt * 32 + kq * 4);
            sA[kq * 4 + 0][row] = v.x;
            sA[kq * 4 + 1][row] = v.y;
            sA[kq * 4 + 2][row] = v.z;
            sA[kq * 4 + 3][row] = v.w;
        }
        // B tile: W rows, transposed into sB[k][n]
        #pragma unroll
        for (int rr = 0; rr < 4; ++rr) {
            int row = rowq + rr * 32;
            float4 v = *(const float4*)(W + (size_t)row * K2 + kt * 32 + kq * 4);
            sB[kq * 4 + 0][row] = v.x;
            sB[kq * 4 + 1][row] = v.y;
            sB[kq * 4 + 2][row] = v.z;
            sB[kq * 4 + 3][row] = v.w;
        }
        __syncthreads();

        #pragma unroll
        for (int k = 0; k < 32; ++k) {
            float4 a0 = *(const float4*)&sA[k][tm];
            float4 a1 = *(const float4*)&sA[k][tm + 4];
            float4 b0 = *(const float4*)&sB[k][tn];
            float4 b1 = *(const float4*)&sB[k][tn + 4];
            float a[8] = {a0.x, a0.y, a0.z, a0.w, a1.x, a1.y, a1.z, a1.w};
            float b[8] = {b0.x, b0.y, b0.z, b0.w, b1.x, b1.y, b1.z, b1.w};
            #pragma unroll
            for (int mi = 0; mi < 8; ++mi)
                #pragma unroll
                for (int ni = 0; ni < 8; ++ni)
                    acc[mi][ni] += a[mi] * b[ni];
        }
    }

    // Epilogue: bias + relu
    #pragma unroll
    for (int mi = 0; mi < 8; ++mi) {
        float* orow = out + (size_t)(m0 + tm + mi) * COUT + tn;
        #pragma unroll
        for (int ni = 0; ni < 8; ++ni) {
            float v = acc[mi][ni] + sbias[tn + ni];
            orow[ni] = fmaxf(v, 0.0f);
        }
    }
}

extern "C" void kernel_launch(void* const* d_in, const int* in_sizes, int n_in,
                              void* d_out, int out_size)
{
    const float* signal = (const float*)d_in[0];
    const int*   pidx   = (const int*)  d_in[1];
    const float* convk  = (const float*)d_in[2];
    const float* W      = (const float*)d_in[3];
    const float* bias   = (const float*)d_in[4];
    float* out = (float*)d_out;

    ypow_kernel<<<BV / 4, 128>>>(signal, pidx, convk);
    out_gemm_kernel<<<BV / 128, 256>>>(W, bias, out);
}

// round 2
// speedup vs baseline: 2.4231x; 2.4231x over previous
#include <cuda_runtime.h>
#include <cstdint>

#define B_    8
#define V_    4096
#define P_    32
#define CIN   64
#define COUT  128
#define BV    (B_ * V_)      // 32768
#define K2    512            // Cin*R*(Lmax+1)

// 64 MB scratch for ypow [BV][K2], k = c*8 + r*4 + l (matches W flattening)
__device__ float g_ypow[(size_t)BV * K2];

__device__ __forceinline__ uint32_t f2tf32(float x) {
    uint32_t r;
    asm("cvt.rna.tf32.f32 %0, %1;" : "=r"(r) : "f"(x));
    return r;
}

__device__ __forceinline__ void mma_tf32(float& d0, float& d1, float& d2, float& d3,
                                         uint32_t a0, uint32_t a1, uint32_t a2, uint32_t a3,
                                         uint32_t b0, uint32_t b1) {
    asm volatile(
        "mma.sync.aligned.m16n8k8.row.col.f32.tf32.tf32.f32 "
        "{%0,%1,%2,%3}, {%4,%5,%6,%7}, {%8,%9}, {%0,%1,%2,%3};"
        : "+f"(d0), "+f"(d1), "+f"(d2), "+f"(d3)
        : "r"(a0), "r"(a1), "r"(a2), "r"(a3), "r"(b0), "r"(b1));
}

__device__ __forceinline__ float sqclip(float x) {
    return sqrtf(fmaxf(x, 1e-4f));
}

// ---------------------------------------------------------------------------
// Kernel 1: per-(b,v) gather + C[c=64][rn=32] = S^T(64x32) * A(32x32) via tf32
// mma, then square + per-l sums + sqrt -> g_ypow.  One CTA (128 thr) per bv.
// ---------------------------------------------------------------------------
#define SST_STR 36   // S^T [c=64][p=32] pad: A-frag LDS (4g+tig) conflict-free
#define SA_STR  40   // A   [p=32][rn=32] pad: B-frag LDS (8tig+g) conflict-free
#define SY_STR  33

__global__ __launch_bounds__(128, 4)
void ypow_kernel(const float* __restrict__ signal,
                 const int*   __restrict__ pidx,
                 const float* __restrict__ convk)
{
    __shared__ uint32_t smem[64 * SST_STR + 32 * SA_STR];  // 14336 B
    uint32_t* sST = smem;                  // [64][36]
    uint32_t* sA  = smem + 64 * SST_STR;   // [32][40]
    uint32_t* sY  = smem;                  // reuse: [64][33] (2112 <= 3584)

    const int bv   = blockIdx.x;
    const int tid  = threadIdx.x;
    const int warp = tid >> 5;
    const int lane = tid & 31;
    const int g    = lane >> 2;
    const int tig  = lane & 3;

    // Stage conv kernel A[p][rn] (tf32) -- coalesced float4
    {
        const float4* src = (const float4*)(convk + (size_t)bv * 1024);
        #pragma unroll
        for (int it = 0; it < 2; ++it) {
            int f = tid + it * 128;          // 0..255 float4s
            float4 v = src[f];
            int p = f >> 3, rn = (f & 7) * 4;
            uint4 u;
            u.x = f2tf32(v.x); u.y = f2tf32(v.y); u.z = f2tf32(v.z); u.w = f2tf32(v.w);
            *(uint4*)&sA[p * SA_STR + rn] = u;
        }
    }
    // Gather signal rows, store TRANSPOSED as S^T[c][p] (tf32)
    {
        const int pr = tid >> 2;             // patch row 0..31
        const int q  = tid & 3;
        const int2 ip = ((const int2*)pidx)[bv * P_ + pr];
        const float4* srow = (const float4*)(signal + ((size_t)ip.x * V_ + (size_t)ip.y) * CIN);
        #pragma unroll
        for (int j = 0; j < 4; ++j) {
            float4 v = srow[j * 4 + q];
            int c = j * 16 + q * 4;
            sST[(c + 0) * SST_STR + pr] = f2tf32(v.x);
            sST[(c + 1) * SST_STR + pr] = f2tf32(v.y);
            sST[(c + 2) * SST_STR + pr] = f2tf32(v.z);
            sST[(c + 3) * SST_STR + pr] = f2tf32(v.w);
        }
    }
    __syncthreads();

    // Warp owns m-tile (16 c-rows): mt = warp*16; all 4 n-tiles, K=32 (4 k-steps)
    const int mt = warp * 16;
    float acc[4][4];
    #pragma unroll
    for (int i = 0; i < 4; ++i)
        #pragma unroll
        for (int j = 0; j < 4; ++j) acc[i][j] = 0.0f;

    #pragma unroll
    for (int ks = 0; ks < 4; ++ks) {
        const int k0 = ks * 8;
        uint32_t a0 = sST[(mt + g)     * SST_STR + k0 + tig];
        uint32_t a1 = sST[(mt + g + 8) * SST_STR + k0 + tig];
        uint32_t a2 = sST[(mt + g)     * SST_STR + k0 + tig + 4];
        uint32_t a3 = sST[(mt + g + 8) * SST_STR + k0 + tig + 4];
        #pragma unroll
        for (int nt = 0; nt < 4; ++nt) {
            uint32_t b0 = sA[(k0 + tig)     * SA_STR + nt * 8 + g];
            uint32_t b1 = sA[(k0 + tig + 4) * SA_STR + nt * 8 + g];
            mma_tf32(acc[nt][0], acc[nt][1], acc[nt][2], acc[nt][3],
                     a0, a1, a2, a3, b0, b1);
        }
    }
    __syncthreads();   // everyone done reading staged inputs

    // Store y to smem [c][rn], stride 33
    #pragma unroll
    for (int nt = 0; nt < 4; ++nt) {
        int col = nt * 8 + 2 * tig;
        sY[(mt + g)     * SY_STR + col]     = __float_as_uint(acc[nt][0]);
        sY[(mt + g)     * SY_STR + col + 1] = __float_as_uint(acc[nt][1]);
        sY[(mt + g + 8) * SY_STR + col]     = __float_as_uint(acc[nt][2]);
        sY[(mt + g + 8) * SY_STR + col + 1] = __float_as_uint(acc[nt][3]);
    }
    __syncthreads();

    // Epilogue: thread t -> (c = t>>1, r = t&1); 16 n values; l-sums; sqrt
    {
        const int c = tid >> 1, r = tid & 1;
        const uint32_t* row = sY + c * SY_STR + r * 16;
        float q[16];
        #pragma unroll
        for (int j = 0; j < 16; ++j) {
            float v = __uint_as_float(row[j]);
            q[j] = v * v;
        }
        float l0 = q[0];
        float l1 = q[1] + q[2] + q[3];
        float l2 = q[4] + q[5] + q[6] + q[7] + q[8];
        float l3 = q[9] + q[10] + q[11] + q[12] + q[13] + q[14] + q[15];
        float4 o;
        o.x = sqclip(l0); o.y = sqclip(l1); o.z = sqclip(l2); o.w = sqclip(l3);
        ((float4*)g_ypow)[(size_t)bv * 128 + tid] = o;   // k = c*8 + r*4 + l
    }
}

// ---------------------------------------------------------------------------
// Kernel 2: out[32768,128] = ypow[32768,512] * W[128,512]^T + bias, relu.
// tf32 mma, CTA tile 128x128, kT=32, 8 warps each 32(m) x 64(n).
// ---------------------------------------------------------------------------
#define SAY_STR 36

__global__ __launch_bounds__(256, 2)
void out_gemm_kernel(const float* __restrict__ W,
                     const float* __restrict__ bias,
                     float* __restrict__ out)
{
    __shared__ uint32_t sAy[128 * SAY_STR];   // ypow tile [m=128][k=32] pad 36
    __shared__ uint32_t sW [128 * SAY_STR];   // W    tile [n=128][k=32] pad 36
    __shared__ float sbias[COUT];

    const int tid  = threadIdx.x;
    const int warp = tid >> 5;
    const int lane = tid & 31;
    const int g    = lane >> 2;
    const int tig  = lane & 3;
    const int wm   = warp >> 1;       // 0..3 -> 32 m-rows each
    const int wn   = warp & 1;        // 0..1 -> 64 n-cols each
    const int m0   = blockIdx.x * 128;

    if (tid < COUT) sbias[tid] = bias[tid];

    float acc[2][8][4];
    #pragma unroll
    for (int a = 0; a < 2; ++a)
        #pragma unroll
        for (int b = 0; b < 8; ++b)
            #pragma unroll
            for (int c = 0; c < 4; ++c) acc[a][b][c] = 0.0f;

    const float4* yp4 = (const float4*)g_ypow;
    const float4* W4  = (const float4*)W;

    for (int kt = 0; kt < 16; ++kt) {
        __syncthreads();
        // Stage ypow tile: 128 rows x 32 k (1024 float4 loads -> tf32)
        #pragma unroll
        for (int it = 0; it < 4; ++it) {
            int f = tid + it * 256;            // 0..1023
            int row = f >> 3, kq = f & 7;
            float4 v = yp4[(size_t)(m0 + row) * 128 + kt * 8 + kq];
            uint4 u;
            u.x = f2tf32(v.x); u.y = f2tf32(v.y); u.z = f2tf32(v.z); u.w = f2tf32(v.w);
            *(uint4*)&sAy[row * SAY_STR + kq * 4] = u;
        }
        // Stage W tile (row-major [n][k], B-frag access is conflict-free)
        #pragma unroll
        for (int it = 0; it < 4; ++it) {
            int f = tid + it * 256;
            int n = f >> 3, kq = f & 7;
            float4 v = W4[(size_t)n * 128 + kt * 8 + kq];
            uint4 u;
            u.x = f2tf32(v.x); u.y = f2tf32(v.y); u.z = f2tf32(v.z); u.w = f2tf32(v.w);
            *(uint4*)&sW[n * SAY_STR + kq * 4] = u;
        }
        __syncthreads();

        #pragma unroll
        for (int ks = 0; ks < 4; ++ks) {
            const int k0 = ks * 8;
            uint32_t a[2][4];
            #pragma unroll
            for (int mi = 0; mi < 2; ++mi) {
                int mr = wm * 32 + mi * 16;
                a[mi][0] = sAy[(mr + g)     * SAY_STR + k0 + tig];
                a[mi][1] = sAy[(mr + g + 8) * SAY_STR + k0 + tig];
                a[mi][2] = sAy[(mr + g)     * SAY_STR + k0 + tig + 4];
                a[mi][3] = sAy[(mr + g + 8) * SAY_STR + k0 + tig + 4];
            }
            #pragma unroll
            for (int nt = 0; nt < 8; ++nt) {
                int n = wn * 64 + nt * 8 + g;
                uint32_t b0 = sW[n * SAY_STR + k0 + tig];
                uint32_t b1 = sW[n * SAY_STR + k0 + tig + 4];
                mma_tf32(acc[0][nt][0], acc[0][nt][1], acc[0][nt][2], acc[0][nt][3],
                         a[0][0], a[0][1], a[0][2], a[0][3], b0, b1);
                mma_tf32(acc[1][nt][0], acc[1][nt][1], acc[1][nt][2], acc[1][nt][3],
                         a[1][0], a[1][1], a[1][2], a[1][3], b0, b1);
            }
        }
    }

    // Epilogue: bias + relu, float2 stores (sector-aligned)
    #pragma unroll
    for (int mi = 0; mi < 2; ++mi) {
        int row = m0 + wm * 32 + mi * 16 + g;
        #pragma unroll
        for (int nt = 0; nt < 8; ++nt) {
            int col = wn * 64 + nt * 8 + 2 * tig;
            float b0 = sbias[col], b1 = sbias[col + 1];
            float2 v0, v1;
            v0.x = fmaxf(acc[mi][nt][0] + b0, 0.0f);
            v0.y = fmaxf(acc[mi][nt][1] + b1, 0.0f);
            v1.x = fmaxf(acc[mi][nt][2] + b0, 0.0f);
            v1.y = fmaxf(acc[mi][nt][3] + b1, 0.0f);
            *(float2*)(out + (size_t)row * COUT + col)       = v0;
            *(float2*)(out + (size_t)(row + 8) * COUT + col) = v1;
        }
    }
}

extern "C" void kernel_launch(void* const* d_in, const int* in_sizes, int n_in,
                              void* d_out, int out_size)
{
    const float* signal = (const float*)d_in[0];
    const int*   pidx   = (const int*)  d_in[1];
    const float* convk  = (const float*)d_in[2];
    const float* W      = (const float*)d_in[3];
    const float* bias   = (const float*)d_in[4];
    float* out = (float*)d_out;

    ypow_kernel<<<BV, 128>>>(signal, pidx, convk);
    out_gemm_kernel<<<BV / 128, 256>>>(W, bias, out);
}